// round 7
// baseline (speedup 1.0000x reference)
#include <cuda_runtime.h>
#include <cstdint>
#include <cstddef>

#define DEVINL __device__ __forceinline__

// Problem constants
constexpr int Bc = 4;
constexpr int Tc = 1024;
constexpr int Ec = 1024;
constexpr int Hc = 16;
constexpr float SCALING       = 0.17677669529663687f;   // 32^-0.5
constexpr float LAMBDA_INIT_F = 0.7836057665316245f;    // 0.8 - 0.6*exp(-3.6)
constexpr float ONE_MINUS_LI  = 1.0f - LAMBDA_INIT_F;

// Scratch (allocation-free rule: __device__ globals)
__device__ float g_lam;
__device__ float g_qbuf[Bc * Tc * Ec];
__device__ float g_kbuf[Bc * Tc * Ec];
__device__ float g_vbuf[Bc * Tc * Ec];
__device__ float g_abuf[Bc * Tc * Ec];

// ---------------- packed f32x2 helpers (sm_103a FFMA2 pipe) ----------------
DEVINL void ffma2(unsigned long long &acc, unsigned long long a, unsigned long long b) {
    asm("fma.rn.f32x2 %0, %1, %2, %0;" : "+l"(acc) : "l"(a), "l"(b));
}
DEVINL void fmul2(unsigned long long &a, unsigned long long b) {
    asm("mul.rn.f32x2 %0, %0, %1;" : "+l"(a) : "l"(b));
}
DEVINL unsigned long long splat2(float x) {
    unsigned long long r;
    asm("mov.b64 %0, {%1, %1};" : "=l"(r) : "f"(x));
    return r;
}
DEVINL float2 u2f(unsigned long long v) {
    float2 f;
    asm("mov.b64 {%0, %1}, %2;" : "=f"(f.x), "=f"(f.y) : "l"(v));
    return f;
}

// =====================================================================
// SGEMM:  C[M,N] = scale * (A[M,K] @ W[N,K]^T)
// 128x128 block tile, BK=16, 256 threads, 8x8 micro-tile, double-buffered smem
// =====================================================================
DEVINL void gemm_ldg(const float* __restrict__ A, const float* __restrict__ W,
                     int m0, int n0, int K, int k0, int tid,
                     float4 &pa0, float4 &pa1, float4 &pb0, float4 &pb1)
{
    const int row0 = tid >> 2;      // 0..63
    const int seg  = tid & 3;       // 0..3
    pa0 = *reinterpret_cast<const float4*>(&A[(size_t)(m0 + row0     ) * K + k0 + seg * 4]);
    pa1 = *reinterpret_cast<const float4*>(&A[(size_t)(m0 + row0 + 64) * K + k0 + seg * 4]);
    pb0 = *reinterpret_cast<const float4*>(&W[(size_t)(n0 + row0     ) * K + k0 + seg * 4]);
    pb1 = *reinterpret_cast<const float4*>(&W[(size_t)(n0 + row0 + 64) * K + k0 + seg * 4]);
}

DEVINL void gemm_sts(float (&As)[16][132], float (&Bs)[16][132], int tid,
                     const float4 &pa0, const float4 &pa1,
                     const float4 &pb0, const float4 &pb1)
{
    const int row0 = tid >> 2;
    const int seg  = tid & 3;
    As[seg*4+0][row0] = pa0.x;  As[seg*4+1][row0] = pa0.y;
    As[seg*4+2][row0] = pa0.z;  As[seg*4+3][row0] = pa0.w;
    As[seg*4+0][row0+64] = pa1.x;  As[seg*4+1][row0+64] = pa1.y;
    As[seg*4+2][row0+64] = pa1.z;  As[seg*4+3][row0+64] = pa1.w;
    Bs[seg*4+0][row0] = pb0.x;  Bs[seg*4+1][row0] = pb0.y;
    Bs[seg*4+2][row0] = pb0.z;  Bs[seg*4+3][row0] = pb0.w;
    Bs[seg*4+0][row0+64] = pb1.x;  Bs[seg*4+1][row0+64] = pb1.y;
    Bs[seg*4+2][row0+64] = pb1.z;  Bs[seg*4+3][row0+64] = pb1.w;
}

DEVINL void gemm_compute(const float (&As)[16][132], const float (&Bs)[16][132],
                         int ty, int tx, unsigned long long (&acc)[8][4])
{
    #pragma unroll
    for (int kk = 0; kk < 16; kk++) {
        const float4 a0 = *reinterpret_cast<const float4*>(&As[kk][ty*8]);
        const float4 a1 = *reinterpret_cast<const float4*>(&As[kk][ty*8+4]);
        const ulonglong2 b0 = *reinterpret_cast<const ulonglong2*>(&Bs[kk][tx*8]);
        const ulonglong2 b1 = *reinterpret_cast<const ulonglong2*>(&Bs[kk][tx*8+4]);
        const float av[8] = {a0.x, a0.y, a0.z, a0.w, a1.x, a1.y, a1.z, a1.w};
        #pragma unroll
        for (int i = 0; i < 8; i++) {
            unsigned long long s = splat2(av[i]);
            ffma2(acc[i][0], s, b0.x);
            ffma2(acc[i][1], s, b0.y);
            ffma2(acc[i][2], s, b1.x);
            ffma2(acc[i][3], s, b1.y);
        }
    }
}

__global__ __launch_bounds__(256)
void sgemm_nt(const float* __restrict__ A, const float* __restrict__ W,
              float* __restrict__ C, int M, int N, int K, float scale)
{
    __shared__ __align__(16) float As[2][16][132];
    __shared__ __align__(16) float Bs[2][16][132];
    const int tid = threadIdx.x;
    const int ty = tid >> 4, tx = tid & 15;
    const int m0 = blockIdx.y * 128;
    const int n0 = blockIdx.x * 128;

    unsigned long long acc[8][4];
    #pragma unroll
    for (int i = 0; i < 8; i++) {
        acc[i][0] = 0ull; acc[i][1] = 0ull; acc[i][2] = 0ull; acc[i][3] = 0ull;
    }

    float4 pa0, pa1, pb0, pb1;
    gemm_ldg(A, W, m0, n0, K, 0, tid, pa0, pa1, pb0, pb1);
    gemm_sts(As[0], Bs[0], tid, pa0, pa1, pb0, pb1);
    __syncthreads();

    const int steps = K >> 4;
    for (int ks = 0; ks < steps; ks++) {
        const int buf = ks & 1;
        if (ks + 1 < steps)
            gemm_ldg(A, W, m0, n0, K, (ks + 1) * 16, tid, pa0, pa1, pb0, pb1);
        gemm_compute(As[buf], Bs[buf], ty, tx, acc);
        if (ks + 1 < steps)
            gemm_sts(As[buf ^ 1], Bs[buf ^ 1], tid, pa0, pa1, pb0, pb1);
        __syncthreads();
    }

    #pragma unroll
    for (int i = 0; i < 8; i++) {
        const float2 t0 = u2f(acc[i][0]);
        const float2 t1 = u2f(acc[i][1]);
        const float2 t2 = u2f(acc[i][2]);
        const float2 t3 = u2f(acc[i][3]);
        const float4 w0 = make_float4(t0.x*scale, t0.y*scale, t1.x*scale, t1.y*scale);
        const float4 w1 = make_float4(t2.x*scale, t2.y*scale, t3.x*scale, t3.y*scale);
        const size_t off = (size_t)(m0 + ty*8 + i) * N + n0 + tx*8;
        *reinterpret_cast<float4*>(&C[off])     = w0;
        *reinterpret_cast<float4*>(&C[off + 4]) = w1;
    }
}

// =====================================================================
// lambda scalar:  lam = exp(dot(lq1,lk1)) - exp(dot(lq2,lk2)) + LAMBDA_INIT
// =====================================================================
__global__ void lambda_kernel(const float* __restrict__ lq1, const float* __restrict__ lk1,
                              const float* __restrict__ lq2, const float* __restrict__ lk2)
{
    const int lane = threadIdx.x;   // 32 threads, D = 32
    float v1 = lq1[lane] * lk1[lane];
    float v2 = lq2[lane] * lk2[lane];
    #pragma unroll
    for (int off = 16; off > 0; off >>= 1) {
        v1 += __shfl_xor_sync(0xffffffffu, v1, off);
        v2 += __shfl_xor_sync(0xffffffffu, v2, off);
    }
    if (lane == 0)
        g_lam = expf(v1) - expf(v2) + LAMBDA_INIT_F;
}

// =====================================================================
// Differential attention (flash-style, two online-softmax streams per block)
// Block = (b, v-head h, 64 q rows). 256 threads = 16x16; thread owns 4x4 of
// the 64x64 O tile (two register accumulators O0, O1 as f32x2 pairs).
// Smem: Qst[64d][68] (transposed), Kst[64d][68] (transposed),
//       Vs[64][68], Ps[64][65]. Total 68864 B (dynamic).
// =====================================================================
constexpr int QST = 68;       // stride for Qst/Kst/Vs (words)
constexpr int PST = 65;       // stride for Ps
constexpr int ATT_SMEM_BYTES = (3 * 64 * QST + 64 * PST) * 4;

DEVINL void process_stream(const float* __restrict__ qb, const float* __restrict__ kb,
                           const float* __restrict__ vsm, float* __restrict__ psm,
                           int ty, int tx,
                           unsigned long long (&o)[4][2], float (&mr)[4], float (&lr)[4])
{
    // --- S = Q K^T (64x64 tile, D=32) ---
    unsigned long long sacc[4][2] = {0ull, 0ull, 0ull, 0ull, 0ull, 0ull, 0ull, 0ull};
    #pragma unroll
    for (int d = 0; d < 32; d++) {
        const float4 a = *reinterpret_cast<const float4*>(&qb[d * QST + ty * 4]);
        const ulonglong2 bv = *reinterpret_cast<const ulonglong2*>(&kb[d * QST + tx * 4]);
        unsigned long long s;
        s = splat2(a.x); ffma2(sacc[0][0], s, bv.x); ffma2(sacc[0][1], s, bv.y);
        s = splat2(a.y); ffma2(sacc[1][0], s, bv.x); ffma2(sacc[1][1], s, bv.y);
        s = splat2(a.z); ffma2(sacc[2][0], s, bv.x); ffma2(sacc[2][1], s, bv.y);
        s = splat2(a.w); ffma2(sacc[3][0], s, bv.x); ffma2(sacc[3][1], s, bv.y);
    }

    // --- online softmax update (row reductions across the 16 tx lanes) ---
    #pragma unroll
    for (int i = 0; i < 4; i++) {
        const float2 s0 = u2f(sacc[i][0]);
        const float2 s1 = u2f(sacc[i][1]);
        float rm = fmaxf(fmaxf(s0.x, s0.y), fmaxf(s1.x, s1.y));
        rm = fmaxf(rm, __shfl_xor_sync(0xffffffffu, rm, 8));
        rm = fmaxf(rm, __shfl_xor_sync(0xffffffffu, rm, 4));
        rm = fmaxf(rm, __shfl_xor_sync(0xffffffffu, rm, 2));
        rm = fmaxf(rm, __shfl_xor_sync(0xffffffffu, rm, 1));
        const float mnew  = fmaxf(mr[i], rm);
        const float alpha = __expf(mr[i] - mnew);
        const float p0 = __expf(s0.x - mnew);
        const float p1 = __expf(s0.y - mnew);
        const float p2 = __expf(s1.x - mnew);
        const float p3 = __expf(s1.y - mnew);
        float rs = (p0 + p1) + (p2 + p3);
        rs += __shfl_xor_sync(0xffffffffu, rs, 8);
        rs += __shfl_xor_sync(0xffffffffu, rs, 4);
        rs += __shfl_xor_sync(0xffffffffu, rs, 2);
        rs += __shfl_xor_sync(0xffffffffu, rs, 1);
        lr[i] = lr[i] * alpha + rs;
        mr[i] = mnew;
        const unsigned long long al = splat2(alpha);
        fmul2(o[i][0], al);
        fmul2(o[i][1], al);
        float* pr = &psm[(ty * 4 + i) * PST + tx * 4];
        pr[0] = p0; pr[1] = p1; pr[2] = p2; pr[3] = p3;
    }
    __syncthreads();

    // --- O += P @ V (64 kk steps) ---
    #pragma unroll 16
    for (int kk = 0; kk < 64; kk++) {
        const ulonglong2 v = *reinterpret_cast<const ulonglong2*>(&vsm[kk * QST + tx * 4]);
        unsigned long long p;
        p = splat2(psm[(ty*4+0) * PST + kk]); ffma2(o[0][0], p, v.x); ffma2(o[0][1], p, v.y);
        p = splat2(psm[(ty*4+1) * PST + kk]); ffma2(o[1][0], p, v.x); ffma2(o[1][1], p, v.y);
        p = splat2(psm[(ty*4+2) * PST + kk]); ffma2(o[2][0], p, v.x); ffma2(o[2][1], p, v.y);
        p = splat2(psm[(ty*4+3) * PST + kk]); ffma2(o[3][0], p, v.x); ffma2(o[3][1], p, v.y);
    }
    __syncthreads();
}

__global__ __launch_bounds__(256)
void diff_attn_kernel(const float* __restrict__ Qb, const float* __restrict__ Kb,
                      const float* __restrict__ Vb, const float* __restrict__ Gw,
                      float* __restrict__ Ob)
{
    extern __shared__ __align__(16) float sm[];
    float* Qst = sm;                     // [64 d][QST]  (d covers both streams)
    float* Kst = sm + 64 * QST;          // [64 d][QST]
    float* Vs  = sm + 2 * 64 * QST;      // [64 kk][QST]
    float* Ps  = sm + 3 * 64 * QST;      // [64 r][PST]

    const int tid = threadIdx.x;
    const int ty = tid >> 4, tx = tid & 15;
    const int b  = blockIdx.x >> 4;
    const int h  = blockIdx.x & 15;
    const int q0 = blockIdx.y << 6;
    const size_t rowbase = (size_t)b * Tc * Ec;
    const int hoff = h * 64;

    // load 64x64 Q tile, transposed to d-major
    #pragma unroll
    for (int r4 = 0; r4 < 4; r4++) {
        const int idx = tid + 256 * r4;
        const int row = idx >> 4;        // 0..63
        const int seg = idx & 15;        // 0..15
        const float4 v = *reinterpret_cast<const float4*>(
            &Qb[rowbase + (size_t)(q0 + row) * Ec + hoff + seg * 4]);
        Qst[(seg*4+0) * QST + row] = v.x;
        Qst[(seg*4+1) * QST + row] = v.y;
        Qst[(seg*4+2) * QST + row] = v.z;
        Qst[(seg*4+3) * QST + row] = v.w;
    }

    unsigned long long o0[4][2] = {0ull,0ull,0ull,0ull,0ull,0ull,0ull,0ull};
    unsigned long long o1[4][2] = {0ull,0ull,0ull,0ull,0ull,0ull,0ull,0ull};
    float m0r[4], l0r[4], m1r[4], l1r[4];
    #pragma unroll
    for (int i = 0; i < 4; i++) { m0r[i] = m1r[i] = -1e30f; l0r[i] = l1r[i] = 0.0f; }

    __syncthreads();

    for (int kt = 0; kt < 16; kt++) {
        // load K (transposed) and V tiles for 64 keys
        #pragma unroll
        for (int r4 = 0; r4 < 4; r4++) {
            const int idx = tid + 256 * r4;
            const int row = idx >> 4;
            const int seg = idx & 15;
            const size_t ga = rowbase + (size_t)(kt * 64 + row) * Ec + hoff + seg * 4;
            const float4 kv = *reinterpret_cast<const float4*>(&Kb[ga]);
            Kst[(seg*4+0) * QST + row] = kv.x;
            Kst[(seg*4+1) * QST + row] = kv.y;
            Kst[(seg*4+2) * QST + row] = kv.z;
            Kst[(seg*4+3) * QST + row] = kv.w;
            const float4 vv = *reinterpret_cast<const float4*>(&Vb[ga]);
            *reinterpret_cast<float4*>(&Vs[row * QST + seg * 4]) = vv;
        }
        __syncthreads();

        // stream 0 uses d channels [0,32), stream 1 uses [32,64)
        process_stream(Qst,            Kst,            Vs, Ps, ty, tx, o0, m0r, l0r);
        process_stream(Qst + 32 * QST, Kst + 32 * QST, Vs, Ps, ty, tx, o1, m1r, l1r);
    }

    // epilogue: normalize, differential subtract, per-head RMSNorm, affine g
    const float lam = g_lam;
    const float4 gv = *reinterpret_cast<const float4*>(&Gw[tx * 4]);
    #pragma unroll
    for (int i = 0; i < 4; i++) {
        const float c0 = 1.0f / l0r[i];
        const float c1 = lam / l1r[i];
        const float2 a0 = u2f(o0[i][0]);
        const float2 a1 = u2f(o0[i][1]);
        const float2 b0 = u2f(o1[i][0]);
        const float2 b1 = u2f(o1[i][1]);
        const float v0 = a0.x * c0 - b0.x * c1;
        const float v1 = a0.y * c0 - b0.y * c1;
        const float v2 = a1.x * c0 - b1.x * c1;
        const float v3 = a1.y * c0 - b1.y * c1;
        float ss = (v0*v0 + v1*v1) + (v2*v2 + v3*v3);
        ss += __shfl_xor_sync(0xffffffffu, ss, 8);
        ss += __shfl_xor_sync(0xffffffffu, ss, 4);
        ss += __shfl_xor_sync(0xffffffffu, ss, 2);
        ss += __shfl_xor_sync(0xffffffffu, ss, 1);
        const float rn = rsqrtf(ss * (1.0f / 64.0f) + 1e-5f) * ONE_MINUS_LI;
        const float4 ov = make_float4(v0 * rn * gv.x, v1 * rn * gv.y,
                                      v2 * rn * gv.z, v3 * rn * gv.w);
        *reinterpret_cast<float4*>(
            &Ob[rowbase + (size_t)(q0 + ty*4 + i) * Ec + hoff + tx * 4]) = ov;
    }
}

// =====================================================================
// launch
// =====================================================================
extern "C" void kernel_launch(void* const* d_in, const int* in_sizes, int n_in,
                              void* d_out, int out_size)
{
    (void)in_sizes; (void)n_in; (void)out_size;
    const float* x   = (const float*)d_in[0];
    const float* Wq  = (const float*)d_in[1];
    const float* Wk  = (const float*)d_in[2];
    const float* Wv  = (const float*)d_in[3];
    const float* Wo  = (const float*)d_in[4];
    const float* lq1 = (const float*)d_in[5];
    const float* lk1 = (const float*)d_in[6];
    const float* lq2 = (const float*)d_in[7];
    const float* lk2 = (const float*)d_in[8];
    const float* gw  = (const float*)d_in[9];
    float* out = (float*)d_out;

    void *qp, *kp, *vp, *ap;
    cudaGetSymbolAddress(&qp, g_qbuf);
    cudaGetSymbolAddress(&kp, g_kbuf);
    cudaGetSymbolAddress(&vp, g_vbuf);
    cudaGetSymbolAddress(&ap, g_abuf);

    cudaFuncSetAttribute(diff_attn_kernel,
                         cudaFuncAttributeMaxDynamicSharedMemorySize, ATT_SMEM_BYTES);

    const dim3 ggrid(Ec / 128, (Bc * Tc) / 128);   // (8, 32)
    const dim3 gblk(256);

    sgemm_nt<<<ggrid, gblk>>>(x, Wq, (float*)qp, Bc*Tc, Ec, Ec, SCALING);
    sgemm_nt<<<ggrid, gblk>>>(x, Wk, (float*)kp, Bc*Tc, Ec, Ec, 1.0f);
    sgemm_nt<<<ggrid, gblk>>>(x, Wv, (float*)vp, Bc*Tc, Ec, Ec, 1.0f);
    lambda_kernel<<<1, 32>>>(lq1, lk1, lq2, lk2);
    diff_attn_kernel<<<dim3(Bc * Hc, Tc / 64), 256, ATT_SMEM_BYTES>>>(
        (const float*)qp, (const float*)kp, (const float*)vp, gw, (float*)ap);
    sgemm_nt<<<ggrid, gblk>>>((const float*)ap, Wo, out, Bc*Tc, Ec, Ec, 1.0f);
}

// round 8
// speedup vs baseline: 1.0023x; 1.0023x over previous
#include <cuda_runtime.h>
#include <cstdint>
#include <cstddef>

#define DEVINL __device__ __forceinline__

// Problem constants
constexpr int Bc = 4;
constexpr int Tc = 1024;
constexpr int Ec = 1024;
constexpr int Hc = 16;
constexpr float SCALING       = 0.17677669529663687f;   // 32^-0.5
constexpr float LAMBDA_INIT_F = 0.7836057665316245f;    // 0.8 - 0.6*exp(-3.6)
constexpr float ONE_MINUS_LI  = 1.0f - LAMBDA_INIT_F;

// Scratch (allocation-free rule: __device__ globals)
__device__ float g_lam;
__device__ float g_qbuf[Bc * Tc * Ec];
__device__ float g_kbuf[Bc * Tc * Ec];
__device__ float g_vbuf[Bc * Tc * Ec];
__device__ float g_abuf[Bc * Tc * Ec];

// ---------------- packed f32x2 helpers (sm_103a FFMA2 pipe) ----------------
DEVINL void ffma2(unsigned long long &acc, unsigned long long a, unsigned long long b) {
    asm("fma.rn.f32x2 %0, %1, %2, %0;" : "+l"(acc) : "l"(a), "l"(b));
}
DEVINL void fmul2(unsigned long long &a, unsigned long long b) {
    asm("mul.rn.f32x2 %0, %0, %1;" : "+l"(a) : "l"(b));
}
DEVINL unsigned long long splat2(float x) {
    unsigned long long r;
    asm("mov.b64 %0, {%1, %1};" : "=l"(r) : "f"(x));
    return r;
}
DEVINL float2 u2f(unsigned long long v) {
    float2 f;
    asm("mov.b64 {%0, %1}, %2;" : "=f"(f.x), "=f"(f.y) : "l"(v));
    return f;
}

// =====================================================================
// SGEMM:  C[M,N] = scale * (A[M,K] @ W[N,K]^T)
// 128x128 block tile, BK=16, 256 threads, 8x8 micro-tile, double-buffered smem
// =====================================================================
DEVINL void gemm_ldg(const float* __restrict__ A, const float* __restrict__ W,
                     int m0, int n0, int K, int k0, int tid,
                     float4 &pa0, float4 &pa1, float4 &pb0, float4 &pb1)
{
    const int row0 = tid >> 2;      // 0..63
    const int seg  = tid & 3;       // 0..3
    pa0 = *reinterpret_cast<const float4*>(&A[(size_t)(m0 + row0     ) * K + k0 + seg * 4]);
    pa1 = *reinterpret_cast<const float4*>(&A[(size_t)(m0 + row0 + 64) * K + k0 + seg * 4]);
    pb0 = *reinterpret_cast<const float4*>(&W[(size_t)(n0 + row0     ) * K + k0 + seg * 4]);
    pb1 = *reinterpret_cast<const float4*>(&W[(size_t)(n0 + row0 + 64) * K + k0 + seg * 4]);
}

DEVINL void gemm_sts(float (&As)[16][132], float (&Bs)[16][132], int tid,
                     const float4 &pa0, const float4 &pa1,
                     const float4 &pb0, const float4 &pb1)
{
    const int row0 = tid >> 2;
    const int seg  = tid & 3;
    As[seg*4+0][row0] = pa0.x;  As[seg*4+1][row0] = pa0.y;
    As[seg*4+2][row0] = pa0.z;  As[seg*4+3][row0] = pa0.w;
    As[seg*4+0][row0+64] = pa1.x;  As[seg*4+1][row0+64] = pa1.y;
    As[seg*4+2][row0+64] = pa1.z;  As[seg*4+3][row0+64] = pa1.w;
    Bs[seg*4+0][row0] = pb0.x;  Bs[seg*4+1][row0] = pb0.y;
    Bs[seg*4+2][row0] = pb0.z;  Bs[seg*4+3][row0] = pb0.w;
    Bs[seg*4+0][row0+64] = pb1.x;  Bs[seg*4+1][row0+64] = pb1.y;
    Bs[seg*4+2][row0+64] = pb1.z;  Bs[seg*4+3][row0+64] = pb1.w;
}

DEVINL void gemm_compute(const float (&As)[16][132], const float (&Bs)[16][132],
                         int ty, int tx, unsigned long long (&acc)[8][4])
{
    #pragma unroll
    for (int kk = 0; kk < 16; kk++) {
        const float4 a0 = *reinterpret_cast<const float4*>(&As[kk][ty*8]);
        const float4 a1 = *reinterpret_cast<const float4*>(&As[kk][ty*8+4]);
        const ulonglong2 b0 = *reinterpret_cast<const ulonglong2*>(&Bs[kk][tx*8]);
        const ulonglong2 b1 = *reinterpret_cast<const ulonglong2*>(&Bs[kk][tx*8+4]);
        const float av[8] = {a0.x, a0.y, a0.z, a0.w, a1.x, a1.y, a1.z, a1.w};
        #pragma unroll
        for (int i = 0; i < 8; i++) {
            unsigned long long s = splat2(av[i]);
            ffma2(acc[i][0], s, b0.x);
            ffma2(acc[i][1], s, b0.y);
            ffma2(acc[i][2], s, b1.x);
            ffma2(acc[i][3], s, b1.y);
        }
    }
}

__global__ __launch_bounds__(256)
void sgemm_nt(const float* __restrict__ A, const float* __restrict__ W,
              float* __restrict__ C, int M, int N, int K, float scale)
{
    __shared__ __align__(16) float As[2][16][132];
    __shared__ __align__(16) float Bs[2][16][132];
    const int tid = threadIdx.x;
    const int ty = tid >> 4, tx = tid & 15;
    const int m0 = blockIdx.y * 128;
    const int n0 = blockIdx.x * 128;

    unsigned long long acc[8][4];
    #pragma unroll
    for (int i = 0; i < 8; i++) {
        acc[i][0] = 0ull; acc[i][1] = 0ull; acc[i][2] = 0ull; acc[i][3] = 0ull;
    }

    float4 pa0, pa1, pb0, pb1;
    gemm_ldg(A, W, m0, n0, K, 0, tid, pa0, pa1, pb0, pb1);
    gemm_sts(As[0], Bs[0], tid, pa0, pa1, pb0, pb1);
    __syncthreads();

    const int steps = K >> 4;
    for (int ks = 0; ks < steps; ks++) {
        const int buf = ks & 1;
        if (ks + 1 < steps)
            gemm_ldg(A, W, m0, n0, K, (ks + 1) * 16, tid, pa0, pa1, pb0, pb1);
        gemm_compute(As[buf], Bs[buf], ty, tx, acc);
        if (ks + 1 < steps)
            gemm_sts(As[buf ^ 1], Bs[buf ^ 1], tid, pa0, pa1, pb0, pb1);
        __syncthreads();
    }

    #pragma unroll
    for (int i = 0; i < 8; i++) {
        const float2 t0 = u2f(acc[i][0]);
        const float2 t1 = u2f(acc[i][1]);
        const float2 t2 = u2f(acc[i][2]);
        const float2 t3 = u2f(acc[i][3]);
        const float4 w0 = make_float4(t0.x*scale, t0.y*scale, t1.x*scale, t1.y*scale);
        const float4 w1 = make_float4(t2.x*scale, t2.y*scale, t3.x*scale, t3.y*scale);
        const size_t off = (size_t)(m0 + ty*8 + i) * N + n0 + tx*8;
        *reinterpret_cast<float4*>(&C[off])     = w0;
        *reinterpret_cast<float4*>(&C[off + 4]) = w1;
    }
}

// =====================================================================
// lambda scalar:  lam = exp(dot(lq1,lk1)) - exp(dot(lq2,lk2)) + LAMBDA_INIT
// =====================================================================
__global__ void lambda_kernel(const float* __restrict__ lq1, const float* __restrict__ lk1,
                              const float* __restrict__ lq2, const float* __restrict__ lk2)
{
    const int lane = threadIdx.x;   // 32 threads, D = 32
    float v1 = lq1[lane] * lk1[lane];
    float v2 = lq2[lane] * lk2[lane];
    #pragma unroll
    for (int off = 16; off > 0; off >>= 1) {
        v1 += __shfl_xor_sync(0xffffffffu, v1, off);
        v2 += __shfl_xor_sync(0xffffffffu, v2, off);
    }
    if (lane == 0)
        g_lam = expf(v1) - expf(v2) + LAMBDA_INIT_F;
}

// =====================================================================
// Differential attention (flash-style, two online-softmax streams per block)
// Block = (b, v-head h, 64 q rows). 256 threads = 16x16; thread owns 4x4 of
// the 64x64 O tile (two register accumulators O0, O1 as f32x2 pairs).
// Smem: Qst[64d][68] (transposed), Kst[64d][68] (transposed),
//       Vs[64][68], Ps[64][65]. Total 68864 B (dynamic).
// =====================================================================
constexpr int QST = 68;       // stride for Qst/Kst/Vs (words)
constexpr int PST = 65;       // stride for Ps
constexpr int ATT_SMEM_BYTES = (3 * 64 * QST + 64 * PST) * 4;

DEVINL void process_stream(const float* __restrict__ qb, const float* __restrict__ kb,
                           const float* __restrict__ vsm, float* __restrict__ psm,
                           int ty, int tx,
                           unsigned long long (&o)[4][2], float (&mr)[4], float (&lr)[4])
{
    // --- S = Q K^T (64x64 tile, D=32) ---
    unsigned long long sacc[4][2] = {0ull, 0ull, 0ull, 0ull, 0ull, 0ull, 0ull, 0ull};
    #pragma unroll
    for (int d = 0; d < 32; d++) {
        const float4 a = *reinterpret_cast<const float4*>(&qb[d * QST + ty * 4]);
        const ulonglong2 bv = *reinterpret_cast<const ulonglong2*>(&kb[d * QST + tx * 4]);
        unsigned long long s;
        s = splat2(a.x); ffma2(sacc[0][0], s, bv.x); ffma2(sacc[0][1], s, bv.y);
        s = splat2(a.y); ffma2(sacc[1][0], s, bv.x); ffma2(sacc[1][1], s, bv.y);
        s = splat2(a.z); ffma2(sacc[2][0], s, bv.x); ffma2(sacc[2][1], s, bv.y);
        s = splat2(a.w); ffma2(sacc[3][0], s, bv.x); ffma2(sacc[3][1], s, bv.y);
    }

    // --- online softmax update (row reductions across the 16 tx lanes) ---
    #pragma unroll
    for (int i = 0; i < 4; i++) {
        const float2 s0 = u2f(sacc[i][0]);
        const float2 s1 = u2f(sacc[i][1]);
        float rm = fmaxf(fmaxf(s0.x, s0.y), fmaxf(s1.x, s1.y));
        rm = fmaxf(rm, __shfl_xor_sync(0xffffffffu, rm, 8));
        rm = fmaxf(rm, __shfl_xor_sync(0xffffffffu, rm, 4));
        rm = fmaxf(rm, __shfl_xor_sync(0xffffffffu, rm, 2));
        rm = fmaxf(rm, __shfl_xor_sync(0xffffffffu, rm, 1));
        const float mnew  = fmaxf(mr[i], rm);
        const float alpha = __expf(mr[i] - mnew);
        const float p0 = __expf(s0.x - mnew);
        const float p1 = __expf(s0.y - mnew);
        const float p2 = __expf(s1.x - mnew);
        const float p3 = __expf(s1.y - mnew);
        float rs = (p0 + p1) + (p2 + p3);
        rs += __shfl_xor_sync(0xffffffffu, rs, 8);
        rs += __shfl_xor_sync(0xffffffffu, rs, 4);
        rs += __shfl_xor_sync(0xffffffffu, rs, 2);
        rs += __shfl_xor_sync(0xffffffffu, rs, 1);
        lr[i] = lr[i] * alpha + rs;
        mr[i] = mnew;
        const unsigned long long al = splat2(alpha);
        fmul2(o[i][0], al);
        fmul2(o[i][1], al);
        float* pr = &psm[(ty * 4 + i) * PST + tx * 4];
        pr[0] = p0; pr[1] = p1; pr[2] = p2; pr[3] = p3;
    }
    __syncthreads();

    // --- O += P @ V (64 kk steps) ---
    #pragma unroll 16
    for (int kk = 0; kk < 64; kk++) {
        const ulonglong2 v = *reinterpret_cast<const ulonglong2*>(&vsm[kk * QST + tx * 4]);
        unsigned long long p;
        p = splat2(psm[(ty*4+0) * PST + kk]); ffma2(o[0][0], p, v.x); ffma2(o[0][1], p, v.y);
        p = splat2(psm[(ty*4+1) * PST + kk]); ffma2(o[1][0], p, v.x); ffma2(o[1][1], p, v.y);
        p = splat2(psm[(ty*4+2) * PST + kk]); ffma2(o[2][0], p, v.x); ffma2(o[2][1], p, v.y);
        p = splat2(psm[(ty*4+3) * PST + kk]); ffma2(o[3][0], p, v.x); ffma2(o[3][1], p, v.y);
    }
    __syncthreads();
}

__global__ __launch_bounds__(256)
void diff_attn_kernel(const float* __restrict__ Qb, const float* __restrict__ Kb,
                      const float* __restrict__ Vb, const float* __restrict__ Gw,
                      float* __restrict__ Ob)
{
    extern __shared__ __align__(16) float sm[];
    float* Qst = sm;                     // [64 d][QST]  (d covers both streams)
    float* Kst = sm + 64 * QST;          // [64 d][QST]
    float* Vs  = sm + 2 * 64 * QST;      // [64 kk][QST]
    float* Ps  = sm + 3 * 64 * QST;      // [64 r][PST]

    const int tid = threadIdx.x;
    const int ty = tid >> 4, tx = tid & 15;
    const int b  = blockIdx.x >> 4;
    const int h  = blockIdx.x & 15;
    const int q0 = blockIdx.y << 6;
    const size_t rowbase = (size_t)b * Tc * Ec;
    const int hoff = h * 64;

    // load 64x64 Q tile, transposed to d-major
    #pragma unroll
    for (int r4 = 0; r4 < 4; r4++) {
        const int idx = tid + 256 * r4;
        const int row = idx >> 4;        // 0..63
        const int seg = idx & 15;        // 0..15
        const float4 v = *reinterpret_cast<const float4*>(
            &Qb[rowbase + (size_t)(q0 + row) * Ec + hoff + seg * 4]);
        Qst[(seg*4+0) * QST + row] = v.x;
        Qst[(seg*4+1) * QST + row] = v.y;
        Qst[(seg*4+2) * QST + row] = v.z;
        Qst[(seg*4+3) * QST + row] = v.w;
    }

    unsigned long long o0[4][2] = {0ull,0ull,0ull,0ull,0ull,0ull,0ull,0ull};
    unsigned long long o1[4][2] = {0ull,0ull,0ull,0ull,0ull,0ull,0ull,0ull};
    float m0r[4], l0r[4], m1r[4], l1r[4];
    #pragma unroll
    for (int i = 0; i < 4; i++) { m0r[i] = m1r[i] = -1e30f; l0r[i] = l1r[i] = 0.0f; }

    __syncthreads();

    for (int kt = 0; kt < 16; kt++) {
        // load K (transposed) and V tiles for 64 keys
        #pragma unroll
        for (int r4 = 0; r4 < 4; r4++) {
            const int idx = tid + 256 * r4;
            const int row = idx >> 4;
            const int seg = idx & 15;
            const size_t ga = rowbase + (size_t)(kt * 64 + row) * Ec + hoff + seg * 4;
            const float4 kv = *reinterpret_cast<const float4*>(&Kb[ga]);
            Kst[(seg*4+0) * QST + row] = kv.x;
            Kst[(seg*4+1) * QST + row] = kv.y;
            Kst[(seg*4+2) * QST + row] = kv.z;
            Kst[(seg*4+3) * QST + row] = kv.w;
            const float4 vv = *reinterpret_cast<const float4*>(&Vb[ga]);
            *reinterpret_cast<float4*>(&Vs[row * QST + seg * 4]) = vv;
        }
        __syncthreads();

        // stream 0 uses d channels [0,32), stream 1 uses [32,64)
        process_stream(Qst,            Kst,            Vs, Ps, ty, tx, o0, m0r, l0r);
        process_stream(Qst + 32 * QST, Kst + 32 * QST, Vs, Ps, ty, tx, o1, m1r, l1r);
    }

    // epilogue: normalize, differential subtract, per-head RMSNorm, affine g
    const float lam = g_lam;
    const float4 gv = *reinterpret_cast<const float4*>(&Gw[tx * 4]);
    #pragma unroll
    for (int i = 0; i < 4; i++) {
        const float c0 = 1.0f / l0r[i];
        const float c1 = lam / l1r[i];
        const float2 a0 = u2f(o0[i][0]);
        const float2 a1 = u2f(o0[i][1]);
        const float2 b0 = u2f(o1[i][0]);
        const float2 b1 = u2f(o1[i][1]);
        const float v0 = a0.x * c0 - b0.x * c1;
        const float v1 = a0.y * c0 - b0.y * c1;
        const float v2 = a1.x * c0 - b1.x * c1;
        const float v3 = a1.y * c0 - b1.y * c1;
        float ss = (v0*v0 + v1*v1) + (v2*v2 + v3*v3);
        ss += __shfl_xor_sync(0xffffffffu, ss, 8);
        ss += __shfl_xor_sync(0xffffffffu, ss, 4);
        ss += __shfl_xor_sync(0xffffffffu, ss, 2);
        ss += __shfl_xor_sync(0xffffffffu, ss, 1);
        const float rn = rsqrtf(ss * (1.0f / 64.0f) + 1e-5f) * ONE_MINUS_LI;
        const float4 ov = make_float4(v0 * rn * gv.x, v1 * rn * gv.y,
                                      v2 * rn * gv.z, v3 * rn * gv.w);
        *reinterpret_cast<float4*>(
            &Ob[rowbase + (size_t)(q0 + ty*4 + i) * Ec + hoff + tx * 4]) = ov;
    }
}

// =====================================================================
// launch
// =====================================================================
extern "C" void kernel_launch(void* const* d_in, const int* in_sizes, int n_in,
                              void* d_out, int out_size)
{
    (void)in_sizes; (void)n_in; (void)out_size;
    const float* x   = (const float*)d_in[0];
    const float* Wq  = (const float*)d_in[1];
    const float* Wk  = (const float*)d_in[2];
    const float* Wv  = (const float*)d_in[3];
    const float* Wo  = (const float*)d_in[4];
    const float* lq1 = (const float*)d_in[5];
    const float* lk1 = (const float*)d_in[6];
    const float* lq2 = (const float*)d_in[7];
    const float* lk2 = (const float*)d_in[8];
    const float* gw  = (const float*)d_in[9];
    float* out = (float*)d_out;

    void *qp, *kp, *vp, *ap;
    cudaGetSymbolAddress(&qp, g_qbuf);
    cudaGetSymbolAddress(&kp, g_kbuf);
    cudaGetSymbolAddress(&vp, g_vbuf);
    cudaGetSymbolAddress(&ap, g_abuf);

    cudaFuncSetAttribute(diff_attn_kernel,
                         cudaFuncAttributeMaxDynamicSharedMemorySize, ATT_SMEM_BYTES);

    const dim3 ggrid(Ec / 128, (Bc * Tc) / 128);   // (8, 32)
    const dim3 gblk(256);

    sgemm_nt<<<ggrid, gblk>>>(x, Wq, (float*)qp, Bc*Tc, Ec, Ec, SCALING);
    sgemm_nt<<<ggrid, gblk>>>(x, Wk, (float*)kp, Bc*Tc, Ec, Ec, 1.0f);
    sgemm_nt<<<ggrid, gblk>>>(x, Wv, (float*)vp, Bc*Tc, Ec, Ec, 1.0f);
    lambda_kernel<<<1, 32>>>(lq1, lk1, lq2, lk2);
    diff_attn_kernel<<<dim3(Bc * Hc, Tc / 64), 256, ATT_SMEM_BYTES>>>(
        (const float*)qp, (const float*)kp, (const float*)vp, gw, (float*)ap);
    sgemm_nt<<<ggrid, gblk>>>((const float*)ap, Wo, out, Bc*Tc, Ec, Ec, 1.0f);
}